// round 10
// baseline (speedup 1.0000x reference)
#include <cuda_runtime.h>
#include <cuda_bf16.h>

// out[t, :] = W[x[t], :] + b   for t in [0, 8192), D = 2048
//
// Model (R9 post-mortem): all variants pin at DRAM ~77MB mixed r/w @ 3.9TB/s
// -> HBM read/write turnaround wall. Fix: invert L2 residency. Output (64MB)
// stays L2-resident across graph replays via default write-allocate stores
// (dirty lines re-dirtied in place, steady-state writeback ~0). W reads are
// evict-first (__ldcs) so the streaming 62MB of rows passes through L2
// without displacing output. Steady-state DRAM = ~64MB of PURE READS.

#define D_MODEL 2048
#define D4      (D_MODEL / 4)   // 512 float4 per row
#define TOKENS  8192
#define TPC     2

__global__ __launch_bounds__(256, 8)
void embed_gather_kernel(const int* __restrict__ x,
                         const float4* __restrict__ W4,
                         const float4* __restrict__ b4,
                         float4* __restrict__ out4) {
    const int t0 = blockIdx.x * TPC;

    const long long r0 = (long long)x[t0 + 0];
    const long long r1 = (long long)x[t0 + 1];

    const int c0 = threadIdx.x;
    const int c1 = threadIdx.x + 256;

    const float4 bb0 = b4[c0];
    const float4 bb1 = b4[c1];

    // 4 independent W gathers, front-batched, EVICT-FIRST (streaming)
    float4 v00 = __ldcs(W4 + r0 * D4 + c0);
    float4 v01 = __ldcs(W4 + r0 * D4 + c1);
    float4 v10 = __ldcs(W4 + r1 * D4 + c0);
    float4 v11 = __ldcs(W4 + r1 * D4 + c1);

    v00.x += bb0.x; v00.y += bb0.y; v00.z += bb0.z; v00.w += bb0.w;
    v01.x += bb1.x; v01.y += bb1.y; v01.z += bb1.z; v01.w += bb1.w;
    v10.x += bb0.x; v10.y += bb0.y; v10.z += bb0.z; v10.w += bb0.w;
    v11.x += bb1.x; v11.y += bb1.y; v11.z += bb1.z; v11.w += bb1.w;

    // default stores: write-allocate, KEEP output resident in L2
    float4* __restrict__ dst = out4 + (long long)t0 * D4;
    dst[c0]      = v00;
    dst[c1]      = v01;
    dst[D4 + c0] = v10;
    dst[D4 + c1] = v11;
}

extern "C" void kernel_launch(void* const* d_in, const int* in_sizes, int n_in,
                              void* d_out, int out_size) {
    const int*    x = (const int*)d_in[0];        // [4, 2048] int32
    const float4* W = (const float4*)d_in[1];     // [50257, 2048] f32
    const float4* b = (const float4*)d_in[2];     // [2048] f32
    float4* out = (float4*)d_out;                 // [4, 2048, 2048] f32

    embed_gather_kernel<<<TOKENS / TPC, 256>>>(x, W, b, out);
}

// round 11
// speedup vs baseline: 1.1068x; 1.1068x over previous
#include <cuda_runtime.h>
#include <cuda_bf16.h>

// out[t, :] = W[x[t], :] + b   for t in [0, 8192), D = 2048
//
// Roofline verdict (R10): kernel is pinned at the chip-wide LTS (L2) cap —
// 128 MB compulsory L2 traffic (64 MB gather reads + 64 MB output writes) at
// ~6300 B/cyc @ 1095 MHz ≈ 6.9 TB/s -> ~18.5 us floor. Six structurally
// different kernels all measure ~6.6 TB/s L2 traffic regardless of MLP,
// TMA vs LDG, or cache policy (path-independent cap). This version trims
// the last non-traffic slop: single int2 index load per CTA, 32-bit offset
// math, MLP=4 front-batched gathers, evict-first stores.

#define D_MODEL 2048
#define D4      (D_MODEL / 4)   // 512 float4 per row
#define TOKENS  8192
#define TPC     2

__global__ __launch_bounds__(256, 8)
void embed_gather_kernel(const int2* __restrict__ x2,
                         const float4* __restrict__ W4,
                         const float4* __restrict__ b4,
                         float4* __restrict__ out4) {
    // one LDG.64 fetches both token indices for this CTA
    const int2 rr = __ldg(x2 + blockIdx.x);

    const int c0 = threadIdx.x;
    const int c1 = threadIdx.x + 256;

    // 32-bit element offsets: max 50257*512 + 511 < 2^25, safely in range
    const unsigned o0 = (unsigned)rr.x * D4;
    const unsigned o1 = (unsigned)rr.y * D4;

    const float4 bb0 = b4[c0];
    const float4 bb1 = b4[c1];

    // 4 independent W gathers, front-batched (MLP=4; queue-safe: 8*4*4=128<248)
    float4 v00 = W4[o0 + c0];
    float4 v01 = W4[o0 + c1];
    float4 v10 = W4[o1 + c0];
    float4 v11 = W4[o1 + c1];

    v00.x += bb0.x; v00.y += bb0.y; v00.z += bb0.z; v00.w += bb0.w;
    v01.x += bb1.x; v01.y += bb1.y; v01.z += bb1.z; v01.w += bb1.w;
    v10.x += bb0.x; v10.y += bb0.y; v10.z += bb0.z; v10.w += bb0.w;
    v11.x += bb1.x; v11.y += bb1.y; v11.z += bb1.z; v11.w += bb1.w;

    float4* __restrict__ dst = out4 + (unsigned)blockIdx.x * (TPC * D4);
    __stcs(dst + c0, v00);          // evict-first: output stream, don't thrash L2
    __stcs(dst + c1, v01);
    __stcs(dst + D4 + c0, v10);
    __stcs(dst + D4 + c1, v11);
}

extern "C" void kernel_launch(void* const* d_in, const int* in_sizes, int n_in,
                              void* d_out, int out_size) {
    const int2*   x = (const int2*)d_in[0];       // [4, 2048] int32, paired
    const float4* W = (const float4*)d_in[1];     // [50257, 2048] f32
    const float4* b = (const float4*)d_in[2];     // [2048] f32
    float4* out = (float4*)d_out;                 // [4, 2048, 2048] f32

    embed_gather_kernel<<<TOKENS / TPC, 256>>>(x, W, b, out);
}